// round 1
// baseline (speedup 1.0000x reference)
#include <cuda_runtime.h>
#include <cuda_bf16.h>
#include <math.h>

// ---------------- problem constants ----------------
#define Bb        2
#define LSEQ      2048
#define TTOK      4096            // Bb*LSEQ
#define DMODEL    2048
#define DINNER    4096
#define NHEAD     64
#define DHEAD     64
#define NSTATE    128
#define NGRP      8
#define CHUNK     256
#define NCHUNK    8               // LSEQ/CHUNK
#define GN        1024            // NGRP*NSTATE
#define CONVDIM   6144            // DINNER + 2*GN
#define INPROJ    10304           // DINNER + NHEAD + 2*GN + DINNER
// proj column offsets
#define COL_ADT   4096
#define COL_B     4160
#define COL_C     5184
#define COL_GATE  6208
// conv_out column offsets
#define CCOL_B    4096
#define CCOL_C    5120

#define OUT_ELEMS   (TTOK*DMODEL)        // 8388608
#define HFIN_ELEMS  (Bb*NHEAD*NSTATE*DHEAD) // 1048576

// ---------------- scratch (device globals; no allocation) ----------------
__device__ float g_xn[(size_t)TTOK*DMODEL];
__device__ float g_proj[(size_t)TTOK*INPROJ];
__device__ float g_conv[(size_t)TTOK*CONVDIM];
__device__ float g_A[(size_t)TTOK*NHEAD];
__device__ float g_Alast[Bb*NCHUNK*NHEAD];
__device__ float g_states[(size_t)Bb*NCHUNK*NHEAD*NSTATE*DHEAD];
__device__ float g_hprev[(size_t)Bb*NCHUNK*NHEAD*NSTATE*DHEAD];
__device__ float g_Y[(size_t)TTOK*DINNER];
__device__ float g_Yg[(size_t)TTOK*DINNER];

// ---------------- helpers ----------------
__device__ __forceinline__ float block_reduce_sum_256(float v) {
    __shared__ float red[8];
    int lane = threadIdx.x & 31, w = threadIdx.x >> 5;
    #pragma unroll
    for (int o = 16; o; o >>= 1) v += __shfl_xor_sync(0xffffffffu, v, o);
    if (lane == 0) red[w] = v;
    __syncthreads();
    if (w == 0) {
        v = (lane < 8) ? red[lane] : 0.f;
        #pragma unroll
        for (int o = 4; o; o >>= 1) v += __shfl_xor_sync(0xffffffffu, v, o);
        if (lane == 0) red[0] = v;
    }
    __syncthreads();
    return red[0];
}

// ---------------- K1: input rmsnorm ----------------
__global__ __launch_bounds__(256) void k_rms_in(const float* __restrict__ x,
                                                const float* __restrict__ w) {
    int row = blockIdx.x;
    const float* xr = x + (size_t)row * DMODEL;
    float ss = 0.f;
    for (int i = threadIdx.x; i < DMODEL; i += 256) { float v = xr[i]; ss += v * v; }
    float tot = block_reduce_sum_256(ss);
    float r = rsqrtf(tot * (1.f / DMODEL) + 1e-6f);
    for (int i = threadIdx.x; i < DMODEL; i += 256)
        g_xn[(size_t)row * DMODEL + i] = xr[i] * r * w[i];
}

// ---------------- K2/K9: SGEMM  C[M,N] = A[M,K] * B[N,K]^T (+addend) ----------------
// sel==0: A = g_xn, C = g_proj ; sel==1: A = g_Yg, C = Cout
__global__ __launch_bounds__(256) void k_sgemm(int sel,
        const float* __restrict__ Bm, float* __restrict__ Cout,
        const float* __restrict__ addend, int M, int N, int K) {
    __shared__ __align__(16) float As[16][128];
    __shared__ __align__(16) float Bs[16][128];
    const float* A = sel ? g_Yg : g_xn;
    float* C = sel ? Cout : g_proj;

    int n0 = blockIdx.x * 128, m0 = blockIdx.y * 128;
    int tid = threadIdx.x;
    int tx = tid & 15, ty = tid >> 4;
    int lr = tid >> 2, lc = (tid & 3) << 2;

    float acc[8][8];
    #pragma unroll
    for (int i = 0; i < 8; i++)
        #pragma unroll
        for (int j = 0; j < 8; j++) acc[i][j] = 0.f;

    for (int k0 = 0; k0 < K; k0 += 16) {
        #pragma unroll
        for (int p = 0; p < 2; p++) {
            int m = m0 + lr + p * 64;
            float4 v = make_float4(0.f, 0.f, 0.f, 0.f);
            if (m < M) v = *(const float4*)&A[(size_t)m * K + k0 + lc];
            As[lc + 0][lr + p * 64] = v.x;
            As[lc + 1][lr + p * 64] = v.y;
            As[lc + 2][lr + p * 64] = v.z;
            As[lc + 3][lr + p * 64] = v.w;
            int nr = n0 + lr + p * 64;
            float4 u = make_float4(0.f, 0.f, 0.f, 0.f);
            if (nr < N) u = *(const float4*)&Bm[(size_t)nr * K + k0 + lc];
            Bs[lc + 0][lr + p * 64] = u.x;
            Bs[lc + 1][lr + p * 64] = u.y;
            Bs[lc + 2][lr + p * 64] = u.z;
            Bs[lc + 3][lr + p * 64] = u.w;
        }
        __syncthreads();
        #pragma unroll
        for (int k = 0; k < 16; k++) {
            float a[8], b[8];
            *(float4*)&a[0] = *(const float4*)&As[k][ty * 8];
            *(float4*)&a[4] = *(const float4*)&As[k][ty * 8 + 4];
            *(float4*)&b[0] = *(const float4*)&Bs[k][tx * 8];
            *(float4*)&b[4] = *(const float4*)&Bs[k][tx * 8 + 4];
            #pragma unroll
            for (int i = 0; i < 8; i++)
                #pragma unroll
                for (int j = 0; j < 8; j++) acc[i][j] += a[i] * b[j];
        }
        __syncthreads();
    }
    #pragma unroll
    for (int i = 0; i < 8; i++) {
        int m = m0 + ty * 8 + i;
        if (m >= M) continue;
        #pragma unroll
        for (int j = 0; j < 8; j++) {
            int n = n0 + tx * 8 + j;
            if (n < N) {
                float v = acc[i][j];
                if (addend) v += addend[(size_t)m * N + n];
                C[(size_t)m * N + n] = v;
            }
        }
    }
}

// ---------------- K3: depthwise conv4 + bias + rmsnorm + silu ----------------
__global__ __launch_bounds__(256) void k_conv(const float* __restrict__ cw,
        const float* __restrict__ cb, const float* __restrict__ cnw) {
    int t = blockIdx.x;
    int b = t >> 11, l = t & 2047;
    float v[24];
    float ss = 0.f;
    #pragma unroll
    for (int j = 0; j < 24; j++) {
        int c = threadIdx.x + j * 256;
        int pc = (c < DINNER) ? c : c + NHEAD;   // B/C regions shifted past A_dt cols
        float a = cb[c];
        #pragma unroll
        for (int k = 0; k < 4; k++) {
            int lk = l + k - 3;
            if (lk >= 0)
                a += cw[c * 4 + k] * g_proj[(size_t)(b * LSEQ + lk) * INPROJ + pc];
        }
        v[j] = a;
        ss += a * a;
    }
    float tot = block_reduce_sum_256(ss);
    float r = rsqrtf(tot * (1.f / CONVDIM) + 1e-6f);
    #pragma unroll
    for (int j = 0; j < 24; j++) {
        int c = threadIdx.x + j * 256;
        float y = v[j] * r * cnw[c];
        g_conv[(size_t)t * CONVDIM + c] = y / (1.f + expf(-y));   // silu
    }
}

// ---------------- K4: dt = softplus(A_dt @ dt_w^T + dt_b); A = -exp(A_log)*dt ----
__global__ __launch_bounds__(64) void k_dt(const float* __restrict__ dt_w,
        const float* __restrict__ dt_b, const float* __restrict__ A_log) {
    __shared__ float ad[64];
    int t = blockIdx.x, h = threadIdx.x;
    ad[h] = g_proj[(size_t)t * INPROJ + COL_ADT + h];
    __syncthreads();
    float z = dt_b[h];
    #pragma unroll
    for (int k = 0; k < 64; k++) z += ad[k] * dt_w[h * 64 + k];
    float dt = (z > 20.f) ? z : log1pf(expf(z));
    g_A[(size_t)t * NHEAD + h] = -expf(A_log[h]) * dt;
}

// ---------------- K5: per-chunk states[n,d] = sum_t B[t,n]*exp(Alast-Acs[t])*X[t,d]
__global__ __launch_bounds__(256) void k_states() {
    __shared__ __align__(16) float sB[32 * 128];
    __shared__ __align__(16) float sX[32 * 64];
    __shared__ float sA[256];
    __shared__ float sw[256];
    int blk = blockIdx.x;                 // (b*8+c)*64 + h
    int b = blk >> 9, c = (blk >> 6) & 7, h = blk & 63, g = h >> 3;
    int tid = threadIdx.x;
    size_t tokbase = (size_t)(b * LSEQ + c * CHUNK);

    sA[tid] = g_A[(tokbase + tid) * NHEAD + h];
    __syncthreads();
    if (tid == 0) {
        float s = 0.f;
        for (int t = 0; t < 256; t++) { s += sA[t]; sA[t] = s; }
        g_Alast[blk] = s;
    }
    __syncthreads();
    sw[tid] = expf(sA[255] - sA[tid]);
    __syncthreads();

    int n = tid >> 1, dh = tid & 1, db = dh << 5;
    float acc[32];
    #pragma unroll
    for (int j = 0; j < 32; j++) acc[j] = 0.f;

    for (int t0 = 0; t0 < 256; t0 += 32) {
        __syncthreads();
        #pragma unroll
        for (int k = 0; k < 4; k++) {
            int q = tid + k * 256; int j = q >> 5, n4 = (q & 31) << 2;
            *(float4*)&sB[j * 128 + n4] =
                *(const float4*)&g_conv[(tokbase + t0 + j) * CONVDIM + CCOL_B + g * 128 + n4];
        }
        #pragma unroll
        for (int k = 0; k < 2; k++) {
            int q = tid + k * 256; int j = q >> 4, d4 = (q & 15) << 2;
            *(float4*)&sX[j * 64 + d4] =
                *(const float4*)&g_conv[(tokbase + t0 + j) * CONVDIM + h * 64 + d4];
        }
        __syncthreads();
        #pragma unroll
        for (int i = 0; i < 32; i++) {
            float bw = sB[i * 128 + n] * sw[t0 + i];
            const float4* xr = (const float4*)&sX[i * 64 + db];
            #pragma unroll
            for (int j = 0; j < 8; j++) {
                float4 xv = xr[j];
                acc[4 * j + 0] += bw * xv.x;
                acc[4 * j + 1] += bw * xv.y;
                acc[4 * j + 2] += bw * xv.z;
                acc[4 * j + 3] += bw * xv.w;
            }
        }
    }
    size_t ob = ((size_t)blk * NSTATE + n) * DHEAD + db;
    #pragma unroll
    for (int j = 0; j < 8; j++)
        *(float4*)&g_states[ob + 4 * j] =
            make_float4(acc[4 * j], acc[4 * j + 1], acc[4 * j + 2], acc[4 * j + 3]);
}

// ---------------- K6: inter-chunk scan; writes h_prev per chunk + h_final -------
__global__ __launch_bounds__(256) void k_scan(float* __restrict__ hout) {
    int b = blockIdx.x >> 6, h = blockIdx.x & 63;
    int e0 = threadIdx.x * 32;
    float hs[32];
    #pragma unroll
    for (int j = 0; j < 32; j++) hs[j] = 0.f;
    for (int c = 0; c < NCHUNK; c++) {
        int chb = (b * NCHUNK + c) * NHEAD + h;
        float cd = expf(g_Alast[chb]);
        size_t base = (size_t)chb * (NSTATE * DHEAD) + e0;
        #pragma unroll
        for (int j = 0; j < 8; j++) {
            *(float4*)&g_hprev[base + 4 * j] =
                make_float4(hs[4 * j], hs[4 * j + 1], hs[4 * j + 2], hs[4 * j + 3]);
            float4 st = *(const float4*)&g_states[base + 4 * j];
            hs[4 * j + 0] = hs[4 * j + 0] * cd + st.x;
            hs[4 * j + 1] = hs[4 * j + 1] * cd + st.y;
            hs[4 * j + 2] = hs[4 * j + 2] * cd + st.z;
            hs[4 * j + 3] = hs[4 * j + 3] * cd + st.w;
        }
    }
    if (hout) {
        size_t ob = (size_t)(b * NHEAD + h) * (NSTATE * DHEAD) + e0;
        #pragma unroll
        for (int j = 0; j < 8; j++)
            *(float4*)&hout[ob + 4 * j] =
                make_float4(hs[4 * j], hs[4 * j + 1], hs[4 * j + 2], hs[4 * j + 3]);
    }
}

// ---------------- K7: Y = Y_diag + Y_carry per chunk-head ----------------------
__global__ __launch_bounds__(256) void k_ydiag() {
    __shared__ float sAcs[256];
    __shared__ __align__(16) float sCt[32][128];
    __shared__ __align__(16) float sB[32 * 133];   // also reused for h_prev chunks
    __shared__ __align__(16) float sX[32][64];
    __shared__ float sM[32 * 36];
    int blk = blockIdx.x;                 // (b*8+c)*64 + h
    int b = blk >> 9, c = (blk >> 6) & 7, h = blk & 63, g = h >> 3;
    int tid = threadIdx.x;
    size_t tokbase = (size_t)(b * LSEQ + c * CHUNK);
    size_t chb = (size_t)blk;

    sAcs[tid] = g_A[(tokbase + tid) * NHEAD + h];
    __syncthreads();
    if (tid == 0) {
        float s = 0.f;
        for (int t = 0; t < 256; t++) { s += sAcs[t]; sAcs[t] = s; }
    }
    __syncthreads();

    int ty = tid >> 5, tx = tid & 31;
    int bi = tid >> 4, bj = tid & 15;

    for (int t0 = 0; t0 < 8; t0++) {
        __syncthreads();
        // load C tile rows [t0*32, t0*32+32)
        #pragma unroll
        for (int k = 0; k < 4; k++) {
            int q = tid + k * 256; int i = q >> 5, n4 = (q & 31) << 2;
            *(float4*)&sCt[i][n4] =
                *(const float4*)&g_conv[(tokbase + t0 * 32 + i) * CONVDIM + CCOL_C + g * 128 + n4];
        }
        float accD[4][2] = {{0.f,0.f},{0.f,0.f},{0.f,0.f},{0.f,0.f}};
        float acc2[4][2] = {{0.f,0.f},{0.f,0.f},{0.f,0.f},{0.f,0.f}};

        for (int s0 = 0; s0 <= t0; s0++) {
            __syncthreads();
            #pragma unroll
            for (int k = 0; k < 4; k++) {
                int q = tid + k * 256; int j = q >> 5, n4 = (q & 31) << 2;
                float4 v = *(const float4*)&g_conv[(tokbase + s0 * 32 + j) * CONVDIM + CCOL_B + g * 128 + n4];
                sB[j * 133 + n4 + 0] = v.x;
                sB[j * 133 + n4 + 1] = v.y;
                sB[j * 133 + n4 + 2] = v.z;
                sB[j * 133 + n4 + 3] = v.w;
            }
            #pragma unroll
            for (int k = 0; k < 2; k++) {
                int q = tid + k * 256; int j = q >> 4, d4 = (q & 15) << 2;
                *(float4*)&sX[j][d4] =
                    *(const float4*)&g_conv[(tokbase + s0 * 32 + j) * CONVDIM + h * 64 + d4];
            }
            __syncthreads();
            // CB 2x2 micro-tile
            float m00 = 0.f, m01 = 0.f, m10 = 0.f, m11 = 0.f;
            const float* c0p = &sCt[2 * bi][0];
            const float* c1p = &sCt[2 * bi + 1][0];
            const float* b0p = &sB[(2 * bj) * 133];
            const float* b1p = &sB[(2 * bj + 1) * 133];
            #pragma unroll 8
            for (int n = 0; n < 128; n++) {
                float c0 = c0p[n], c1 = c1p[n], bb0 = b0p[n], bb1 = b1p[n];
                m00 += c0 * bb0; m01 += c0 * bb1;
                m10 += c1 * bb0; m11 += c1 * bb1;
            }
            int ti0 = t0 * 32 + 2 * bi, sj0 = s0 * 32 + 2 * bj;
            float at0 = sAcs[ti0], at1 = sAcs[ti0 + 1];
            float as0 = sAcs[sj0], as1 = sAcs[sj0 + 1];
            sM[(2 * bi) * 36 + 2 * bj]         = (sj0     <= ti0    ) ? m00 * expf(at0 - as0) : 0.f;
            sM[(2 * bi) * 36 + 2 * bj + 1]     = (sj0 + 1 <= ti0    ) ? m01 * expf(at0 - as1) : 0.f;
            sM[(2 * bi + 1) * 36 + 2 * bj]     = (sj0     <= ti0 + 1) ? m10 * expf(at1 - as0) : 0.f;
            sM[(2 * bi + 1) * 36 + 2 * bj + 1] = (sj0 + 1 <= ti0 + 1) ? m11 * expf(at1 - as1) : 0.f;
            __syncthreads();
            // accD += M @ X
            #pragma unroll
            for (int k = 0; k < 32; k++) {
                float x0 = sX[k][tx], x1 = sX[k][tx + 32];
                #pragma unroll
                for (int r = 0; r < 4; r++) {
                    float m = sM[(ty + 8 * r) * 36 + k];
                    accD[r][0] += m * x0;
                    accD[r][1] += m * x1;
                }
            }
        }
        // carry: acc2 += (C_t * h_prev), n in two 64-chunks staged into sB
        #pragma unroll
        for (int nh = 0; nh < 2; nh++) {
            __syncthreads();
            #pragma unroll
            for (int k = 0; k < 4; k++) {
                int q = tid + k * 256; int nl = q >> 4, d4 = (q & 15) << 2;
                *(float4*)&sB[nl * 64 + d4] =
                    *(const float4*)&g_hprev[(chb * NSTATE + nh * 64 + nl) * DHEAD + d4];
            }
            __syncthreads();
            #pragma unroll
            for (int k = 0; k < 64; k++) {
                float h0 = sB[k * 64 + tx], h1 = sB[k * 64 + tx + 32];
                int n = nh * 64 + k;
                #pragma unroll
                for (int r = 0; r < 4; r++) {
                    float cr = sCt[ty + 8 * r][n];
                    acc2[r][0] += cr * h0;
                    acc2[r][1] += cr * h1;
                }
            }
        }
        // write Y
        #pragma unroll
        for (int r = 0; r < 4; r++) {
            int t = t0 * 32 + ty + 8 * r;
            float e = expf(sAcs[t]);
            size_t off = (tokbase + t) * DINNER + h * 64;
            g_Y[off + tx]      = accD[r][0] + acc2[r][0] * e;
            g_Y[off + tx + 32] = accD[r][1] + acc2[r][1] * e;
        }
    }
}

// ---------------- K8: out rmsnorm * silu(gate) -> Yg ----------------
__global__ __launch_bounds__(256) void k_gate(const float* __restrict__ onw) {
    int t = blockIdx.x;
    float ss = 0.f;
    for (int i = threadIdx.x; i < DINNER; i += 256) {
        float v = g_Y[(size_t)t * DINNER + i];
        ss += v * v;
    }
    float tot = block_reduce_sum_256(ss);
    float r = rsqrtf(tot * (1.f / DINNER) + 1e-6f);
    for (int i = threadIdx.x; i < DINNER; i += 256) {
        float y = g_Y[(size_t)t * DINNER + i] * r * onw[i];
        float gt = g_proj[(size_t)t * INPROJ + COL_GATE + i];
        g_Yg[(size_t)t * DINNER + i] = y * gt / (1.f + expf(-gt));
    }
}

// ---------------- launch ----------------
extern "C" void kernel_launch(void* const* d_in, const int* in_sizes, int n_in,
                              void* d_out, int out_size) {
    const float* x          = (const float*)d_in[0];
    const float* norm_w     = (const float*)d_in[1];
    const float* in_proj_w  = (const float*)d_in[2];
    const float* conv_w     = (const float*)d_in[3];
    const float* conv_b     = (const float*)d_in[4];
    const float* conv_norm_w= (const float*)d_in[5];
    const float* A_log      = (const float*)d_in[6];
    const float* dt_w       = (const float*)d_in[7];
    const float* dt_b       = (const float*)d_in[8];
    const float* out_norm_w = (const float*)d_in[9];
    const float* out_proj_w = (const float*)d_in[10];
    float* out = (float*)d_out;

    float* hfin = (out_size >= OUT_ELEMS + HFIN_ELEMS) ? (out + OUT_ELEMS) : nullptr;

    k_rms_in<<<TTOK, 256>>>(x, norm_w);
    k_sgemm<<<dim3((INPROJ + 127) / 128, TTOK / 128), 256>>>(
        0, in_proj_w, nullptr, nullptr, TTOK, INPROJ, DMODEL);
    k_conv<<<TTOK, 256>>>(conv_w, conv_b, conv_norm_w);
    k_dt<<<TTOK, 64>>>(dt_w, dt_b, A_log);
    k_states<<<Bb * NCHUNK * NHEAD, 256>>>();
    k_scan<<<Bb * NHEAD, 256>>>(hfin);
    k_ydiag<<<Bb * NCHUNK * NHEAD, 256>>>();
    k_gate<<<TTOK, 256>>>(out_norm_w);
    k_sgemm<<<dim3(DMODEL / 128, TTOK / 128), 256>>>(
        1, out_proj_w, out, x, TTOK, DMODEL, DINNER);
}

// round 5
// speedup vs baseline: 1.7918x; 1.7918x over previous
#include <cuda_runtime.h>
#include <cuda_bf16.h>
#include <math.h>
#include <cstdint>

// ---------------- problem constants ----------------
#define Bb        2
#define LSEQ      2048
#define TTOK      4096            // Bb*LSEQ
#define DMODEL    2048
#define DINNER    4096
#define NHEAD     64
#define DHEAD     64
#define NSTATE    128
#define NGRP      8
#define CHUNK     256
#define NCHUNK    8               // LSEQ/CHUNK
#define GN        1024            // NGRP*NSTATE
#define CONVDIM   6144            // DINNER + 2*GN
#define INPROJ    10304           // DINNER + NHEAD + 2*GN + DINNER
#define INPROJ_PAD 10368          // 81*128
// proj column offsets
#define COL_ADT   4096
#define COL_GATE  6208
// conv_out column offsets
#define CCOL_B    4096
#define CCOL_C    5120

#define OUT_ELEMS   (TTOK*DMODEL)
#define HFIN_ELEMS  (Bb*NHEAD*NSTATE*DHEAD)

// ---------------- scratch (device globals; no allocation) ----------------
// NOTE: these symbols must ONLY be referenced from device code. Passing them
// as kernel arguments from host code silently targets the host shadow (ATS).
__device__ float g_xn[(size_t)TTOK*DMODEL];
__device__ float g_proj[(size_t)TTOK*INPROJ];
__device__ float g_conv[(size_t)TTOK*CONVDIM];
__device__ float g_A[(size_t)TTOK*NHEAD];
__device__ float g_Alast[Bb*NCHUNK*NHEAD];
__device__ float g_states[(size_t)Bb*NCHUNK*NHEAD*NSTATE*DHEAD];
__device__ float g_hprev[(size_t)Bb*NCHUNK*NHEAD*NSTATE*DHEAD];
__device__ float g_Y[(size_t)TTOK*DINNER];
__device__ float g_Yg[(size_t)TTOK*DINNER];
// bf16 split GEMM operands
__device__ __nv_bfloat16 g_a2[(size_t)TTOK*3*DINNER];          // A' (activations), max K'=12288
__device__ __nv_bfloat16 g_b2in[(size_t)INPROJ_PAD*3*DMODEL];  // in_proj weights split
__device__ __nv_bfloat16 g_b2out[(size_t)DMODEL*3*DINNER];     // out_proj weights split

// ---------------- helpers ----------------
__device__ __forceinline__ float block_reduce_sum_256(float v) {
    __shared__ float red[8];
    int lane = threadIdx.x & 31, w = threadIdx.x >> 5;
    #pragma unroll
    for (int o = 16; o; o >>= 1) v += __shfl_xor_sync(0xffffffffu, v, o);
    if (lane == 0) red[w] = v;
    __syncthreads();
    if (w == 0) {
        v = (lane < 8) ? red[lane] : 0.f;
        #pragma unroll
        for (int o = 4; o; o >>= 1) v += __shfl_xor_sync(0xffffffffu, v, o);
        if (lane == 0) red[0] = v;
    }
    __syncthreads();
    return red[0];
}

__device__ __forceinline__ unsigned int s2u(const void* p) {
    unsigned int a;
    asm("{ .reg .u64 t; cvta.to.shared.u64 t, %1; cvt.u32.u64 %0, t; }" : "=r"(a) : "l"(p));
    return a;
}

// ---------------- K1: input rmsnorm ----------------
__global__ __launch_bounds__(256) void k_rms_in(const float* __restrict__ x,
                                                const float* __restrict__ w) {
    int row = blockIdx.x;
    const float* xr = x + (size_t)row * DMODEL;
    float ss = 0.f;
    for (int i = threadIdx.x; i < DMODEL; i += 256) { float v = xr[i]; ss += v * v; }
    float tot = block_reduce_sum_256(ss);
    float r = rsqrtf(tot * (1.f / DMODEL) + 1e-6f);
    for (int i = threadIdx.x; i < DMODEL; i += 256)
        g_xn[(size_t)row * DMODEL + i] = xr[i] * r * w[i];
}

// ---------------- split conversion: src fp32 [R][K] -> dst bf16 [Rpad][3K] -----
// bmode==0 (A operand): [0,K)=hi [K,2K)=hi [2K,3K)=lo
// bmode==1 (B operand): [0,K)=hi [K,2K)=lo [2K,3K)=hi
// so sum over K3 = Ahi*Bhi + Ahi*Blo + Alo*Bhi  (drops only lo*lo)
// dsel: 0 -> g_a2, 1 -> g_b2in, 2 -> g_b2out  (device-side symbol selection!)
__global__ __launch_bounds__(256) void k_cvt(int sel, int bmode, int dsel,
                                             const float* __restrict__ srcp,
                                             int R, int K) {
    const float* src = (sel == 0) ? g_xn : (sel == 1) ? g_Yg : srcp;
    __nv_bfloat16* dst = (dsel == 0) ? g_a2 : (dsel == 1) ? g_b2in : g_b2out;
    size_t idx = (size_t)blockIdx.x * 256 + threadIdx.x;
    int row = (int)(idx / K);
    int k = (int)(idx - (size_t)row * K);
    float v = (row < R) ? src[(size_t)row * K + k] : 0.f;
    __nv_bfloat16 hi = __float2bfloat16(v);
    __nv_bfloat16 lo = __float2bfloat16(v - __bfloat162float(hi));
    size_t base = (size_t)row * (3 * (size_t)K);
    dst[base + k] = hi;
    dst[base + K + k] = bmode ? lo : hi;
    dst[base + 2 * K + k] = bmode ? hi : lo;
}

// ---------------- K2/K9: bf16 tensor-core GEMM --------------------------------
// C[M,N] = A'[M,K3] * B'[Npad,K3]^T  (+ addend), bf16 in / fp32 accumulate
// selc==0: C = g_proj (device symbol); selc==1: C = Cout (runtime pointer)
__global__ __launch_bounds__(256) void k_hgemm(int selb, int selc,
        float* __restrict__ Cout,
        const float* __restrict__ addend, int M, int N, int K3) {
    const __nv_bfloat16* A2 = g_a2;
    const __nv_bfloat16* B2 = selb ? g_b2out : g_b2in;
    float* C = selc ? Cout : g_proj;
    __shared__ __align__(16) __nv_bfloat16 sA[2][128][40];
    __shared__ __align__(16) __nv_bfloat16 sB[2][128][40];
    int tid = threadIdx.x, lane = tid & 31, warp = tid >> 5;
    int wm = warp >> 2, wn = warp & 3;
    int m0 = blockIdx.y * 128, n0 = blockIdx.x * 128;

    float acc[4][4][4];
    #pragma unroll
    for (int mi = 0; mi < 4; mi++)
        #pragma unroll
        for (int ni = 0; ni < 4; ni++)
            #pragma unroll
            for (int q = 0; q < 4; q++) acc[mi][ni][q] = 0.f;

    uint4 ra[2], rb[2];
    int nK = K3 >> 5;

    // prologue load tile 0
    #pragma unroll
    for (int i = 0; i < 2; i++) {
        int idx = tid + i * 256;
        int row = idx >> 2, c8 = (idx & 3) * 8;
        ra[i] = *(const uint4*)&A2[(size_t)(m0 + row) * K3 + c8];
        rb[i] = *(const uint4*)&B2[(size_t)(n0 + row) * K3 + c8];
    }
    #pragma unroll
    for (int i = 0; i < 2; i++) {
        int idx = tid + i * 256;
        int row = idx >> 2, c8 = (idx & 3) * 8;
        *(uint4*)&sA[0][row][c8] = ra[i];
        *(uint4*)&sB[0][row][c8] = rb[i];
    }
    __syncthreads();

    for (int kt = 0; kt < nK; kt++) {
        int buf = kt & 1;
        if (kt + 1 < nK) {
            size_t kk = (size_t)(kt + 1) * 32;
            #pragma unroll
            for (int i = 0; i < 2; i++) {
                int idx = tid + i * 256;
                int row = idx >> 2, c8 = (idx & 3) * 8;
                ra[i] = *(const uint4*)&A2[(size_t)(m0 + row) * K3 + kk + c8];
                rb[i] = *(const uint4*)&B2[(size_t)(n0 + row) * K3 + kk + c8];
            }
        }
        #pragma unroll
        for (int kh = 0; kh < 2; kh++) {
            unsigned int af[4][4], bfr[4][2];
            #pragma unroll
            for (int mi = 0; mi < 4; mi++) {
                unsigned int addr = s2u(&sA[buf][wm * 64 + mi * 16 + (lane & 15)][kh * 16 + (lane >> 4) * 8]);
                asm volatile("ldmatrix.sync.aligned.m8n8.x4.shared.b16 {%0,%1,%2,%3}, [%4];"
                    : "=r"(af[mi][0]), "=r"(af[mi][1]), "=r"(af[mi][2]), "=r"(af[mi][3]) : "r"(addr));
            }
            #pragma unroll
            for (int ni = 0; ni < 4; ni++) {
                unsigned int addr = s2u(&sB[buf][wn * 32 + ni * 8 + (lane & 7)][kh * 16 + ((lane >> 3) & 1) * 8]);
                asm volatile("ldmatrix.sync.aligned.m8n8.x2.shared.b16 {%0,%1}, [%2];"
                    : "=r"(bfr[ni][0]), "=r"(bfr[ni][1]) : "r"(addr));
            }
            #pragma unroll
            for (int mi = 0; mi < 4; mi++)
                #pragma unroll
                for (int ni = 0; ni < 4; ni++)
                    asm volatile("mma.sync.aligned.m16n8k16.row.col.f32.bf16.bf16.f32 "
                        "{%0,%1,%2,%3},{%4,%5,%6,%7},{%8,%9},{%0,%1,%2,%3};"
                        : "+f"(acc[mi][ni][0]), "+f"(acc[mi][ni][1]),
                          "+f"(acc[mi][ni][2]), "+f"(acc[mi][ni][3])
                        : "r"(af[mi][0]), "r"(af[mi][1]), "r"(af[mi][2]), "r"(af[mi][3]),
                          "r"(bfr[ni][0]), "r"(bfr[ni][1]));
        }
        if (kt + 1 < nK) {
            __syncthreads();
            int nb = (kt + 1) & 1;
            #pragma unroll
            for (int i = 0; i < 2; i++) {
                int idx = tid + i * 256;
                int row = idx >> 2, c8 = (idx & 3) * 8;
                *(uint4*)&sA[nb][row][c8] = ra[i];
                *(uint4*)&sB[nb][row][c8] = rb[i];
            }
            __syncthreads();
        }
    }

    #pragma unroll
    for (int mi = 0; mi < 4; mi++) {
        int r = m0 + wm * 64 + mi * 16 + (lane >> 2);
        #pragma unroll
        for (int ni = 0; ni < 4; ni++) {
            int cc = n0 + wn * 32 + ni * 8 + (lane & 3) * 2;
            #pragma unroll
            for (int half = 0; half < 2; half++) {
                int rr = r + half * 8;
                float v0 = acc[mi][ni][half * 2], v1 = acc[mi][ni][half * 2 + 1];
                if (cc < N) {
                    if (addend) v0 += addend[(size_t)rr * N + cc];
                    C[(size_t)rr * N + cc] = v0;
                }
                if (cc + 1 < N) {
                    if (addend) v1 += addend[(size_t)rr * N + cc + 1];
                    C[(size_t)rr * N + cc + 1] = v1;
                }
            }
        }
    }
}

// ---------------- K3: depthwise conv4 + bias + rmsnorm + silu ----------------
__global__ __launch_bounds__(256) void k_conv(const float* __restrict__ cw,
        const float* __restrict__ cb, const float* __restrict__ cnw) {
    int t = blockIdx.x;
    int b = t >> 11, l = t & 2047;
    float v[24];
    float ss = 0.f;
    #pragma unroll
    for (int j = 0; j < 24; j++) {
        int c = threadIdx.x + j * 256;
        int pc = (c < DINNER) ? c : c + NHEAD;
        float a = cb[c];
        #pragma unroll
        for (int k = 0; k < 4; k++) {
            int lk = l + k - 3;
            if (lk >= 0)
                a += cw[c * 4 + k] * g_proj[(size_t)(b * LSEQ + lk) * INPROJ + pc];
        }
        v[j] = a;
        ss += a * a;
    }
    float tot = block_reduce_sum_256(ss);
    float r = rsqrtf(tot * (1.f / CONVDIM) + 1e-6f);
    #pragma unroll
    for (int j = 0; j < 24; j++) {
        int c = threadIdx.x + j * 256;
        float y = v[j] * r * cnw[c];
        g_conv[(size_t)t * CONVDIM + c] = y / (1.f + expf(-y));
    }
}

// ---------------- K4: dt = softplus(A_dt @ dt_w^T + dt_b); A = -exp(A_log)*dt ----
__global__ __launch_bounds__(256) void k_dt(const float* __restrict__ dt_w,
        const float* __restrict__ dt_b, const float* __restrict__ A_log) {
    __shared__ float ad[4][64];
    int sub = threadIdx.x >> 6, h = threadIdx.x & 63;
    int t = blockIdx.x * 4 + sub;
    ad[sub][h] = g_proj[(size_t)t * INPROJ + COL_ADT + h];
    __syncthreads();
    float z = dt_b[h];
    #pragma unroll
    for (int k = 0; k < 64; k++) z += ad[sub][k] * dt_w[h * 64 + k];
    float dt = (z > 20.f) ? z : log1pf(expf(z));
    g_A[(size_t)t * NHEAD + h] = -expf(A_log[h]) * dt;
}

// ---------------- K5: per-chunk states ----------------------------------------
__global__ __launch_bounds__(256) void k_states() {
    __shared__ __align__(16) float sB[32 * 128];
    __shared__ __align__(16) float sX[32 * 64];
    __shared__ float sA[256];
    __shared__ float sw[256];
    int blk = blockIdx.x;
    int b = blk >> 9, c = (blk >> 6) & 7, h = blk & 63, g = h >> 3;
    int tid = threadIdx.x;
    size_t tokbase = (size_t)(b * LSEQ + c * CHUNK);

    sA[tid] = g_A[(tokbase + tid) * NHEAD + h];
    __syncthreads();
    if (tid == 0) {
        float s = 0.f;
        for (int t = 0; t < 256; t++) { s += sA[t]; sA[t] = s; }
        g_Alast[blk] = s;
    }
    __syncthreads();
    sw[tid] = expf(sA[255] - sA[tid]);
    __syncthreads();

    int n = tid >> 1, dh = tid & 1, db = dh << 5;
    float acc[32];
    #pragma unroll
    for (int j = 0; j < 32; j++) acc[j] = 0.f;

    for (int t0 = 0; t0 < 256; t0 += 32) {
        __syncthreads();
        #pragma unroll
        for (int k = 0; k < 4; k++) {
            int q = tid + k * 256; int j = q >> 5, n4 = (q & 31) << 2;
            *(float4*)&sB[j * 128 + n4] =
                *(const float4*)&g_conv[(tokbase + t0 + j) * CONVDIM + CCOL_B + g * 128 + n4];
        }
        #pragma unroll
        for (int k = 0; k < 2; k++) {
            int q = tid + k * 256; int j = q >> 4, d4 = (q & 15) << 2;
            *(float4*)&sX[j * 64 + d4] =
                *(const float4*)&g_conv[(tokbase + t0 + j) * CONVDIM + h * 64 + d4];
        }
        __syncthreads();
        #pragma unroll
        for (int i = 0; i < 32; i++) {
            float bw = sB[i * 128 + n] * sw[t0 + i];
            const float4* xr = (const float4*)&sX[i * 64 + db];
            #pragma unroll
            for (int j = 0; j < 8; j++) {
                float4 xv = xr[j];
                acc[4 * j + 0] += bw * xv.x;
                acc[4 * j + 1] += bw * xv.y;
                acc[4 * j + 2] += bw * xv.z;
                acc[4 * j + 3] += bw * xv.w;
            }
        }
    }
    size_t ob = ((size_t)blk * NSTATE + n) * DHEAD + db;
    #pragma unroll
    for (int j = 0; j < 8; j++)
        *(float4*)&g_states[ob + 4 * j] =
            make_float4(acc[4 * j], acc[4 * j + 1], acc[4 * j + 2], acc[4 * j + 3]);
}

// ---------------- K6: inter-chunk scan -----------------------------------------
__global__ __launch_bounds__(256) void k_scan(float* __restrict__ hout) {
    int b = blockIdx.x >> 6, h = blockIdx.x & 63;
    int e0 = threadIdx.x * 32;
    float hs[32];
    #pragma unroll
    for (int j = 0; j < 32; j++) hs[j] = 0.f;
    for (int c = 0; c < NCHUNK; c++) {
        int chb = (b * NCHUNK + c) * NHEAD + h;
        float cd = expf(g_Alast[chb]);
        size_t base = (size_t)chb * (NSTATE * DHEAD) + e0;
        #pragma unroll
        for (int j = 0; j < 8; j++) {
            *(float4*)&g_hprev[base + 4 * j] =
                make_float4(hs[4 * j], hs[4 * j + 1], hs[4 * j + 2], hs[4 * j + 3]);
            float4 st = *(const float4*)&g_states[base + 4 * j];
            hs[4 * j + 0] = hs[4 * j + 0] * cd + st.x;
            hs[4 * j + 1] = hs[4 * j + 1] * cd + st.y;
            hs[4 * j + 2] = hs[4 * j + 2] * cd + st.z;
            hs[4 * j + 3] = hs[4 * j + 3] * cd + st.w;
        }
    }
    if (hout) {
        size_t ob = (size_t)(b * NHEAD + h) * (NSTATE * DHEAD) + e0;
        #pragma unroll
        for (int j = 0; j < 8; j++)
            *(float4*)&hout[ob + 4 * j] =
                make_float4(hs[4 * j], hs[4 * j + 1], hs[4 * j + 2], hs[4 * j + 3]);
    }
}

// ---------------- K7: Y = Y_diag + Y_carry -------------------------------------
__global__ __launch_bounds__(256) void k_ydiag() {
    __shared__ float sAcs[256];
    __shared__ __align__(16) float sCt[32][128];
    __shared__ __align__(16) float sB[32 * 133];
    __shared__ __align__(16) float sX[32][64];
    __shared__ float sM[32 * 36];
    int blk = blockIdx.x;
    int b = blk >> 9, c = (blk >> 6) & 7, h = blk & 63, g = h >> 3;
    int tid = threadIdx.x;
    size_t tokbase = (size_t)(b * LSEQ + c * CHUNK);
    size_t chb = (size_t)blk;

    sAcs[tid] = g_A[(tokbase + tid) * NHEAD + h];
    __syncthreads();
    if (tid == 0) {
        float s = 0.f;
        for (int t = 0; t < 256; t++) { s += sAcs[t]; sAcs[t] = s; }
    }
    __syncthreads();

    int ty = tid >> 5, tx = tid & 31;
    int bi = tid >> 4, bj = tid & 15;

    for (int t0 = 0; t0 < 8; t0++) {
        __syncthreads();
        #pragma unroll
        for (int k = 0; k < 4; k++) {
            int q = tid + k * 256; int i = q >> 5, n4 = (q & 31) << 2;
            *(float4*)&sCt[i][n4] =
                *(const float4*)&g_conv[(tokbase + t0 * 32 + i) * CONVDIM + CCOL_C + g * 128 + n4];
        }
        float accD[4][2] = {{0.f,0.f},{0.f,0.f},{0.f,0.f},{0.f,0.f}};
        float acc2[4][2] = {{0.f,0.f},{0.f,0.f},{0.f,0.f},{0.f,0.f}};

        for (int s0 = 0; s0 <= t0; s0++) {
            __syncthreads();
            #pragma unroll
            for (int k = 0; k < 4; k++) {
                int q = tid + k * 256; int j = q >> 5, n4 = (q & 31) << 2;
                float4 v = *(const float4*)&g_conv[(tokbase + s0 * 32 + j) * CONVDIM + CCOL_B + g * 128 + n4];
                sB[j * 133 + n4 + 0] = v.x;
                sB[j * 133 + n4 + 1] = v.y;
                sB[j * 133 + n4 + 2] = v.z;
                sB[j * 133 + n4 + 3] = v.w;
            }
            #pragma unroll
            for (int k = 0; k < 2; k++) {
                int q = tid + k * 256; int j = q >> 4, d4 = (q & 15) << 2;
                *(float4*)&sX[j][d4] =
                    *(const float4*)&g_conv[(tokbase + s0 * 32 + j) * CONVDIM + h * 64 + d4];
            }
            __syncthreads();
            float m00 = 0.f, m01 = 0.f, m10 = 0.f, m11 = 0.f;
            const float* c0p = &sCt[2 * bi][0];
            const float* c1p = &sCt[2 * bi + 1][0];
            const float* b0p = &sB[(2 * bj) * 133];
            const float* b1p = &sB[(2 * bj + 1) * 133];
            #pragma unroll 8
            for (int n = 0; n < 128; n++) {
                float c0 = c0p[n], c1 = c1p[n], bb0 = b0p[n], bb1 = b1p[n];
                m00 += c0 * bb0; m01 += c0 * bb1;
                m10 += c1 * bb0; m11 += c1 * bb1;
            }
            int ti0 = t0 * 32 + 2 * bi, sj0 = s0 * 32 + 2 * bj;
            float at0 = sAcs[ti0], at1 = sAcs[ti0 + 1];
            float as0 = sAcs[sj0], as1 = sAcs[sj0 + 1];
            sM[(2 * bi) * 36 + 2 * bj]         = (sj0     <= ti0    ) ? m00 * expf(at0 - as0) : 0.f;
            sM[(2 * bi) * 36 + 2 * bj + 1]     = (sj0 + 1 <= ti0    ) ? m01 * expf(at0 - as1) : 0.f;
            sM[(2 * bi + 1) * 36 + 2 * bj]     = (sj0     <= ti0 + 1) ? m10 * expf(at1 - as0) : 0.f;
            sM[(2 * bi + 1) * 36 + 2 * bj + 1] = (sj0 + 1 <= ti0 + 1) ? m11 * expf(at1 - as1) : 0.f;
            __syncthreads();
            #pragma unroll
            for (int k = 0; k < 32; k++) {
                float x0 = sX[k][tx], x1 = sX[k][tx + 32];
                #pragma unroll
                for (int r = 0; r < 4; r++) {
                    float m = sM[(ty + 8 * r) * 36 + k];
                    accD[r][0] += m * x0;
                    accD[r][1] += m * x1;
                }
            }
        }
        #pragma unroll
        for (int nh = 0; nh < 2; nh++) {
            __syncthreads();
            #pragma unroll
            for (int k = 0; k < 4; k++) {
                int q = tid + k * 256; int nl = q >> 4, d4 = (q & 15) << 2;
                *(float4*)&sB[nl * 64 + d4] =
                    *(const float4*)&g_hprev[(chb * NSTATE + nh * 64 + nl) * DHEAD + d4];
            }
            __syncthreads();
            #pragma unroll
            for (int k = 0; k < 64; k++) {
                float h0 = sB[k * 64 + tx], h1 = sB[k * 64 + tx + 32];
                int n = nh * 64 + k;
                #pragma unroll
                for (int r = 0; r < 4; r++) {
                    float cr = sCt[ty + 8 * r][n];
                    acc2[r][0] += cr * h0;
                    acc2[r][1] += cr * h1;
                }
            }
        }
        #pragma unroll
        for (int r = 0; r < 4; r++) {
            int t = t0 * 32 + ty + 8 * r;
            float e = expf(sAcs[t]);
            size_t off = (tokbase + t) * DINNER + h * 64;
            g_Y[off + tx]      = accD[r][0] + acc2[r][0] * e;
            g_Y[off + tx + 32] = accD[r][1] + acc2[r][1] * e;
        }
    }
}

// ---------------- K8: out rmsnorm * silu(gate) -> Yg ----------------
__global__ __launch_bounds__(256) void k_gate(const float* __restrict__ onw) {
    int t = blockIdx.x;
    float ss = 0.f;
    for (int i = threadIdx.x; i < DINNER; i += 256) {
        float v = g_Y[(size_t)t * DINNER + i];
        ss += v * v;
    }
    float tot = block_reduce_sum_256(ss);
    float r = rsqrtf(tot * (1.f / DINNER) + 1e-6f);
    for (int i = threadIdx.x; i < DINNER; i += 256) {
        float y = g_Y[(size_t)t * DINNER + i] * r * onw[i];
        float gt = g_proj[(size_t)t * INPROJ + COL_GATE + i];
        g_Yg[(size_t)t * DINNER + i] = y * gt / (1.f + expf(-gt));
    }
}

// ---------------- launch ----------------
extern "C" void kernel_launch(void* const* d_in, const int* in_sizes, int n_in,
                              void* d_out, int out_size) {
    const float* x          = (const float*)d_in[0];
    const float* norm_w     = (const float*)d_in[1];
    const float* in_proj_w  = (const float*)d_in[2];
    const float* conv_w     = (const float*)d_in[3];
    const float* conv_b     = (const float*)d_in[4];
    const float* conv_norm_w= (const float*)d_in[5];
    const float* A_log      = (const float*)d_in[6];
    const float* dt_w       = (const float*)d_in[7];
    const float* dt_b       = (const float*)d_in[8];
    const float* out_norm_w = (const float*)d_in[9];
    const float* out_proj_w = (const float*)d_in[10];
    float* out = (float*)d_out;

    float* hfin = (out_size >= OUT_ELEMS + HFIN_ELEMS) ? (out + OUT_ELEMS) : nullptr;

    k_rms_in<<<TTOK, 256>>>(x, norm_w);
    // split conversions for in_proj GEMM (A: [hi|hi|lo], B: [hi|lo|hi])
    k_cvt<<<(unsigned)(((size_t)TTOK * DMODEL) / 256), 256>>>(0, 0, 0, nullptr, TTOK, DMODEL);
    k_cvt<<<(unsigned)(((size_t)INPROJ_PAD * DMODEL) / 256), 256>>>(2, 1, 1, in_proj_w, INPROJ, DMODEL);
    k_hgemm<<<dim3(INPROJ_PAD / 128, TTOK / 128), 256>>>(0, 0, nullptr, nullptr, TTOK, INPROJ, 3 * DMODEL);

    k_conv<<<TTOK, 256>>>(conv_w, conv_b, conv_norm_w);
    k_dt<<<TTOK / 4, 256>>>(dt_w, dt_b, A_log);
    k_states<<<Bb * NCHUNK * NHEAD, 256>>>();
    k_scan<<<Bb * NHEAD, 256>>>(hfin);
    k_ydiag<<<Bb * NCHUNK * NHEAD, 256>>>();
    k_gate<<<TTOK, 256>>>(out_norm_w);

    // split conversions for out_proj GEMM
    k_cvt<<<(unsigned)(((size_t)TTOK * DINNER) / 256), 256>>>(1, 0, 0, nullptr, TTOK, DINNER);
    k_cvt<<<(unsigned)(((size_t)DMODEL * DINNER) / 256), 256>>>(2, 1, 2, out_proj_w, DMODEL, DINNER);
    k_hgemm<<<dim3(DMODEL / 128, TTOK / 128), 256>>>(1, 1, out, x, TTOK, DMODEL, 3 * DINNER);
}

// round 7
// speedup vs baseline: 1.9604x; 1.0941x over previous
#include <cuda_runtime.h>
#include <cuda_bf16.h>
#include <math.h>
#include <cstdint>

// ---------------- problem constants ----------------
#define Bb        2
#define LSEQ      2048
#define TTOK      4096
#define DMODEL    2048
#define DINNER    4096
#define NHEAD     64
#define DHEAD     64
#define NSTATE    128
#define NGRP      8
#define CHUNK     256
#define NCHUNK    8
#define GN        1024
#define CONVDIM   6144
#define INPROJ    10304
#define INPROJ_PAD 10368
#define COL_ADT   4096
#define COL_GATE  6208
#define CCOL_B    4096
#define CCOL_C    5120

#define OUT_ELEMS   (TTOK*DMODEL)
#define HFIN_ELEMS  (Bb*NHEAD*NSTATE*DHEAD)

// ---------------- scratch (device globals; device-code refs ONLY) -------------
__device__ float g_proj[(size_t)TTOK*INPROJ];
__device__ float g_conv[(size_t)TTOK*CONVDIM];
__device__ float g_A[(size_t)TTOK*NHEAD];
__device__ float g_Alast[Bb*NCHUNK*NHEAD];
__device__ float g_states[(size_t)Bb*NCHUNK*NHEAD*NSTATE*DHEAD];
__device__ float g_hprev[(size_t)Bb*NCHUNK*NHEAD*NSTATE*DHEAD];
__device__ float g_Y[(size_t)TTOK*DINNER];
__device__ float g_CB[(size_t)Bb*NCHUNK*NGRP*CHUNK*CHUNK];   // per-(b,c,g) 256x256
__device__ __nv_bfloat16 g_a2[(size_t)TTOK*3*DINNER];
__device__ __nv_bfloat16 g_b2in[(size_t)INPROJ_PAD*3*DMODEL];
__device__ __nv_bfloat16 g_b2out[(size_t)DMODEL*3*DINNER];

// ---------------- helpers ----------------
__device__ __forceinline__ float block_reduce_sum_256(float v) {
    __shared__ float red[8];
    int lane = threadIdx.x & 31, w = threadIdx.x >> 5;
    #pragma unroll
    for (int o = 16; o; o >>= 1) v += __shfl_xor_sync(0xffffffffu, v, o);
    if (lane == 0) red[w] = v;
    __syncthreads();
    if (w == 0) {
        v = (lane < 8) ? red[lane] : 0.f;
        #pragma unroll
        for (int o = 4; o; o >>= 1) v += __shfl_xor_sync(0xffffffffu, v, o);
        if (lane == 0) red[0] = v;
    }
    __syncthreads();
    return red[0];
}

__device__ __forceinline__ unsigned int s2u(const void* p) {
    unsigned int a;
    asm("{ .reg .u64 t; cvta.to.shared.u64 t, %1; cvt.u32.u64 %0, t; }" : "=r"(a) : "l"(p));
    return a;
}

__device__ __forceinline__ void cpa8(unsigned int d, const void* g) {
    asm volatile("cp.async.ca.shared.global [%0], [%1], 8;\n" :: "r"(d), "l"(g));
}

// parallel inclusive scan of 256 values already in registers (one per thread).
// returns inclusive prefix; *tot gets full sum. Needs 9-slot smem scratch.
__device__ __forceinline__ float scan256(float a, float* wps, float* tot) {
    int lane = threadIdx.x & 31, w = threadIdx.x >> 5;
    #pragma unroll
    for (int o = 1; o < 32; o <<= 1) {
        float t = __shfl_up_sync(0xffffffffu, a, o);
        if (lane >= o) a += t;
    }
    if (lane == 31) wps[w] = a;
    __syncthreads();
    if (threadIdx.x == 0) {
        float s = 0.f;
        #pragma unroll
        for (int j = 0; j < 8; j++) { float t = wps[j]; wps[j] = s; s += t; }
        wps[8] = s;
    }
    __syncthreads();
    float r = a + wps[w];
    *tot = wps[8];
    return r;
}

// ---------------- K1: input rmsnorm + bf16 split (A layout [hi|hi|lo]) --------
__global__ __launch_bounds__(256) void k_rms_in(const float* __restrict__ x,
                                                const float* __restrict__ w) {
    int row = blockIdx.x;
    const float* xr = x + (size_t)row * DMODEL;
    float vloc[8];
    float ss = 0.f;
    #pragma unroll
    for (int j = 0; j < 8; j++) { float v = xr[threadIdx.x + j * 256]; vloc[j] = v; ss += v * v; }
    float tot = block_reduce_sum_256(ss);
    float r = rsqrtf(tot * (1.f / DMODEL) + 1e-6f);
    size_t base = (size_t)row * (3 * DMODEL);
    #pragma unroll
    for (int j = 0; j < 8; j++) {
        int k = threadIdx.x + j * 256;
        float v = vloc[j] * r * w[k];
        __nv_bfloat16 hi = __float2bfloat16(v);
        __nv_bfloat16 lo = __float2bfloat16(v - __bfloat162float(hi));
        g_a2[base + k] = hi;
        g_a2[base + DMODEL + k] = hi;
        g_a2[base + 2 * DMODEL + k] = lo;
    }
}

// ---------------- weight split conversion (B layout [hi|lo|hi]) ---------------
__global__ __launch_bounds__(256) void k_cvt(int dsel, const float* __restrict__ srcp,
                                             int R, int K) {
    __nv_bfloat16* dst = (dsel == 1) ? g_b2in : g_b2out;
    size_t idx = (size_t)blockIdx.x * 256 + threadIdx.x;
    int row = (int)(idx / K);
    int k = (int)(idx - (size_t)row * K);
    float v = (row < R) ? srcp[(size_t)row * K + k] : 0.f;
    __nv_bfloat16 hi = __float2bfloat16(v);
    __nv_bfloat16 lo = __float2bfloat16(v - __bfloat162float(hi));
    size_t base = (size_t)row * (3 * (size_t)K);
    dst[base + k] = hi;
    dst[base + K + k] = lo;
    dst[base + 2 * K + k] = hi;
}

// ---------------- bf16 tensor-core GEMM, cp.async 2-stage ---------------------
__global__ __launch_bounds__(256) void k_hgemm(int selb, int selc,
        float* __restrict__ Cout,
        const float* __restrict__ addend, int M, int N, int K3) {
    const __nv_bfloat16* A2 = g_a2;
    const __nv_bfloat16* B2 = selb ? g_b2out : g_b2in;
    float* C = selc ? Cout : g_proj;
    __shared__ __align__(16) __nv_bfloat16 sA[2][128][40];
    __shared__ __align__(16) __nv_bfloat16 sB[2][128][40];
    int tid = threadIdx.x, lane = tid & 31, warp = tid >> 5;
    int wm = warp >> 2, wn = warp & 3;
    int m0 = blockIdx.y * 128, n0 = blockIdx.x * 128;

    float acc[4][4][4];
    #pragma unroll
    for (int mi = 0; mi < 4; mi++)
        #pragma unroll
        for (int ni = 0; ni < 4; ni++)
            #pragma unroll
            for (int q = 0; q < 4; q++) acc[mi][ni][q] = 0.f;

    int nK = K3 >> 5;

    // issue loads for stage st of k-tile kt
    auto issue = [&](int kt, int st) {
        size_t kk = (size_t)kt * 32;
        #pragma unroll
        for (int i = 0; i < 4; i++) {
            int idx = tid + i * 256;
            int row = idx >> 3, c4 = (idx & 7) * 4;
            cpa8(s2u(&sA[st][row][c4]), &A2[(size_t)(m0 + row) * K3 + kk + c4]);
            cpa8(s2u(&sB[st][row][c4]), &B2[(size_t)(n0 + row) * K3 + kk + c4]);
        }
        asm volatile("cp.async.commit_group;\n" ::);
    };

    issue(0, 0);

    for (int kt = 0; kt < nK; kt++) {
        int buf = kt & 1;
        if (kt + 1 < nK) {
            issue(kt + 1, (kt + 1) & 1);
            asm volatile("cp.async.wait_group 1;\n" ::);
        } else {
            asm volatile("cp.async.wait_group 0;\n" ::);
        }
        __syncthreads();
        #pragma unroll
        for (int kh = 0; kh < 2; kh++) {
            unsigned int af[4][4], bfr[4][2];
            #pragma unroll
            for (int mi = 0; mi < 4; mi++) {
                unsigned int addr = s2u(&sA[buf][wm * 64 + mi * 16 + (lane & 15)][kh * 16 + (lane >> 4) * 8]);
                asm volatile("ldmatrix.sync.aligned.m8n8.x4.shared.b16 {%0,%1,%2,%3}, [%4];"
                    : "=r"(af[mi][0]), "=r"(af[mi][1]), "=r"(af[mi][2]), "=r"(af[mi][3]) : "r"(addr));
            }
            #pragma unroll
            for (int ni = 0; ni < 4; ni++) {
                unsigned int addr = s2u(&sB[buf][wn * 32 + ni * 8 + (lane & 7)][kh * 16 + ((lane >> 3) & 1) * 8]);
                asm volatile("ldmatrix.sync.aligned.m8n8.x2.shared.b16 {%0,%1}, [%2];"
                    : "=r"(bfr[ni][0]), "=r"(bfr[ni][1]) : "r"(addr));
            }
            #pragma unroll
            for (int mi = 0; mi < 4; mi++)
                #pragma unroll
                for (int ni = 0; ni < 4; ni++)
                    asm volatile("mma.sync.aligned.m16n8k16.row.col.f32.bf16.bf16.f32 "
                        "{%0,%1,%2,%3},{%4,%5,%6,%7},{%8,%9},{%0,%1,%2,%3};"
                        : "+f"(acc[mi][ni][0]), "+f"(acc[mi][ni][1]),
                          "+f"(acc[mi][ni][2]), "+f"(acc[mi][ni][3])
                        : "r"(af[mi][0]), "r"(af[mi][1]), "r"(af[mi][2]), "r"(af[mi][3]),
                          "r"(bfr[ni][0]), "r"(bfr[ni][1]));
        }
        __syncthreads();
    }

    #pragma unroll
    for (int mi = 0; mi < 4; mi++) {
        int r = m0 + wm * 64 + mi * 16 + (lane >> 2);
        #pragma unroll
        for (int ni = 0; ni < 4; ni++) {
            int cc = n0 + wn * 32 + ni * 8 + (lane & 3) * 2;
            #pragma unroll
            for (int half = 0; half < 2; half++) {
                int rr = r + half * 8;
                float v0 = acc[mi][ni][half * 2], v1 = acc[mi][ni][half * 2 + 1];
                if (cc < N) {
                    if (addend) v0 += addend[(size_t)rr * N + cc];
                    C[(size_t)rr * N + cc] = v0;
                }
                if (cc + 1 < N) {
                    if (addend) v1 += addend[(size_t)rr * N + cc + 1];
                    C[(size_t)rr * N + cc + 1] = v1;
                }
            }
        }
    }
}

// ---------------- K3: depthwise conv4 + bias + rmsnorm + silu ----------------
__global__ __launch_bounds__(256) void k_conv(const float* __restrict__ cw,
        const float* __restrict__ cb, const float* __restrict__ cnw) {
    int t = blockIdx.x;
    int b = t >> 11, l = t & 2047;
    float v[24];
    float ss = 0.f;
    #pragma unroll
    for (int j = 0; j < 24; j++) {
        int c = threadIdx.x + j * 256;
        int pc = (c < DINNER) ? c : c + NHEAD;
        float a = cb[c];
        #pragma unroll
        for (int k = 0; k < 4; k++) {
            int lk = l + k - 3;
            if (lk >= 0)
                a += cw[c * 4 + k] * g_proj[(size_t)(b * LSEQ + lk) * INPROJ + pc];
        }
        v[j] = a;
        ss += a * a;
    }
    float tot = block_reduce_sum_256(ss);
    float r = rsqrtf(tot * (1.f / CONVDIM) + 1e-6f);
    #pragma unroll
    for (int j = 0; j < 24; j++) {
        int c = threadIdx.x + j * 256;
        float y = v[j] * r * cnw[c];
        g_conv[(size_t)t * CONVDIM + c] = y / (1.f + expf(-y));
    }
}

// ---------------- K4: dt path ----------------
__global__ __launch_bounds__(256) void k_dt(const float* __restrict__ dt_w,
        const float* __restrict__ dt_b, const float* __restrict__ A_log) {
    __shared__ float ad[4][64];
    int sub = threadIdx.x >> 6, h = threadIdx.x & 63;
    int t = blockIdx.x * 4 + sub;
    ad[sub][h] = g_proj[(size_t)t * INPROJ + COL_ADT + h];
    __syncthreads();
    float z = dt_b[h];
    #pragma unroll
    for (int k = 0; k < 64; k++) z += ad[sub][k] * dt_w[h * 64 + k];
    float dt = (z > 20.f) ? z : log1pf(expf(z));
    g_A[(size_t)t * NHEAD + h] = -expf(A_log[h]) * dt;
}

// ---------------- K5: per-chunk states ----------------------------------------
__global__ __launch_bounds__(256) void k_states() {
    __shared__ __align__(16) float sB[32 * 128];
    __shared__ __align__(16) float sX[32 * 64];
    __shared__ float sw[256];
    __shared__ float wps[9];
    int blk = blockIdx.x;
    int b = blk >> 9, c = (blk >> 6) & 7, h = blk & 63, g = h >> 3;
    int tid = threadIdx.x;
    size_t tokbase = (size_t)(b * LSEQ + c * CHUNK);

    float av = g_A[(tokbase + tid) * NHEAD + h];
    float atot;
    float acs = scan256(av, wps, &atot);
    sw[tid] = expf(atot - acs);
    if (tid == 0) g_Alast[blk] = atot;
    __syncthreads();

    int n = tid >> 1, dh = tid & 1, db = dh << 5;
    float acc[32];
    #pragma unroll
    for (int j = 0; j < 32; j++) acc[j] = 0.f;

    for (int t0 = 0; t0 < 256; t0 += 32) {
        __syncthreads();
        #pragma unroll
        for (int k = 0; k < 4; k++) {
            int q = tid + k * 256; int j = q >> 5, n4 = (q & 31) << 2;
            *(float4*)&sB[j * 128 + n4] =
                *(const float4*)&g_conv[(tokbase + t0 + j) * CONVDIM + CCOL_B + g * 128 + n4];
        }
        #pragma unroll
        for (int k = 0; k < 2; k++) {
            int q = tid + k * 256; int j = q >> 4, d4 = (q & 15) << 2;
            *(float4*)&sX[j * 64 + d4] =
                *(const float4*)&g_conv[(tokbase + t0 + j) * CONVDIM + h * 64 + d4];
        }
        __syncthreads();
        #pragma unroll
        for (int i = 0; i < 32; i++) {
            float bw = sB[i * 128 + n] * sw[t0 + i];
            const float4* xr = (const float4*)&sX[i * 64 + db];
            #pragma unroll
            for (int j = 0; j < 8; j++) {
                float4 xv = xr[j];
                acc[4 * j + 0] += bw * xv.x;
                acc[4 * j + 1] += bw * xv.y;
                acc[4 * j + 2] += bw * xv.z;
                acc[4 * j + 3] += bw * xv.w;
            }
        }
    }
    size_t ob = ((size_t)blk * NSTATE + n) * DHEAD + db;
    #pragma unroll
    for (int j = 0; j < 8; j++)
        *(float4*)&g_states[ob + 4 * j] =
            make_float4(acc[4 * j], acc[4 * j + 1], acc[4 * j + 2], acc[4 * j + 3]);
}

// ---------------- K6: inter-chunk scan -----------------------------------------
__global__ __launch_bounds__(256) void k_scan(float* __restrict__ hout) {
    int b = blockIdx.x >> 6, h = blockIdx.x & 63;
    int e0 = threadIdx.x * 32;
    float hs[32];
    #pragma unroll
    for (int j = 0; j < 32; j++) hs[j] = 0.f;
    for (int c = 0; c < NCHUNK; c++) {
        int chb = (b * NCHUNK + c) * NHEAD + h;
        float cd = expf(g_Alast[chb]);
        size_t base = (size_t)chb * (NSTATE * DHEAD) + e0;
        #pragma unroll
        for (int j = 0; j < 8; j++) {
            *(float4*)&g_hprev[base + 4 * j] =
                make_float4(hs[4 * j], hs[4 * j + 1], hs[4 * j + 2], hs[4 * j + 3]);
            float4 st = *(const float4*)&g_states[base + 4 * j];
            hs[4 * j + 0] = hs[4 * j + 0] * cd + st.x;
            hs[4 * j + 1] = hs[4 * j + 1] * cd + st.y;
            hs[4 * j + 2] = hs[4 * j + 2] * cd + st.z;
            hs[4 * j + 3] = hs[4 * j + 3] * cd + st.w;
        }
    }
    if (hout) {
        size_t ob = (size_t)(b * NHEAD + h) * (NSTATE * DHEAD) + e0;
        #pragma unroll
        for (int j = 0; j < 8; j++)
            *(float4*)&hout[ob + 4 * j] =
                make_float4(hs[4 * j], hs[4 * j + 1], hs[4 * j + 2], hs[4 * j + 3]);
    }
}

// ---------------- K-CB: per-(b,c,g) raw CB = C @ B^T (tril tiles) --------------
__global__ __launch_bounds__(256) void k_cb() {
    __shared__ __align__(16) float sCt[32][128];
    __shared__ __align__(16) float sB[32 * 133];
    int blk = blockIdx.x;              // b*64 + c*8 + g
    int b = blk >> 6, c = (blk >> 3) & 7, g = blk & 7;
    int tid = threadIdx.x;
    size_t tokbase = (size_t)(b * LSEQ + c * CHUNK);
    size_t cbbase = (size_t)blk * (CHUNK * CHUNK);
    int bi = tid >> 4, bj = tid & 15;

    for (int t0 = 0; t0 < 8; t0++) {
        __syncthreads();
        #pragma unroll
        for (int k = 0; k < 4; k++) {
            int q = tid + k * 256; int i = q >> 5, n4 = (q & 31) << 2;
            *(float4*)&sCt[i][n4] =
                *(const float4*)&g_conv[(tokbase + t0 * 32 + i) * CONVDIM + CCOL_C + g * 128 + n4];
        }
        for (int s0 = 0; s0 <= t0; s0++) {
            __syncthreads();
            #pragma unroll
            for (int k = 0; k < 4; k++) {
                int q = tid + k * 256; int j = q >> 5, n4 = (q & 31) << 2;
                float4 v = *(const float4*)&g_conv[(tokbase + s0 * 32 + j) * CONVDIM + CCOL_B + g * 128 + n4];
                sB[j * 133 + n4 + 0] = v.x;
                sB[j * 133 + n4 + 1] = v.y;
                sB[j * 133 + n4 + 2] = v.z;
                sB[j * 133 + n4 + 3] = v.w;
            }
            __syncthreads();
            float m00 = 0.f, m01 = 0.f, m10 = 0.f, m11 = 0.f;
            const float* c0p = &sCt[2 * bi][0];
            const float* c1p = &sCt[2 * bi + 1][0];
            const float* b0p = &sB[(2 * bj) * 133];
            const float* b1p = &sB[(2 * bj + 1) * 133];
            #pragma unroll 8
            for (int n = 0; n < 128; n++) {
                float c0 = c0p[n], c1 = c1p[n], bb0 = b0p[n], bb1 = b1p[n];
                m00 += c0 * bb0; m01 += c0 * bb1;
                m10 += c1 * bb0; m11 += c1 * bb1;
            }
            size_t r0 = cbbase + (size_t)(t0 * 32 + 2 * bi) * CHUNK + s0 * 32 + 2 * bj;
            *(float2*)&g_CB[r0] = make_float2(m00, m01);
            *(float2*)&g_CB[r0 + CHUNK] = make_float2(m10, m11);
        }
    }
}

// ---------------- K7: Y = Y_diag + Y_carry (CB from global) -------------------
__global__ __launch_bounds__(256) void k_ydiag() {
    __shared__ float sAcs[256];
    __shared__ float wps[9];
    __shared__ __align__(16) float sCtT[128][36];   // transposed C tile
    __shared__ __align__(16) float sM[32][36];      // col-major M: [s][t]
    __shared__ __align__(16) float sX[32][64];
    __shared__ __align__(16) float sH[32 * 64];
    __shared__ float fr[32];
    __shared__ float gc[256];
    int blk = blockIdx.x;
    int b = blk >> 9, c = (blk >> 6) & 7, h = blk & 63, g = h >> 3;
    int tid = threadIdx.x;
    size_t tokbase = (size_t)(b * LSEQ + c * CHUNK);
    size_t chb = (size_t)blk;
    size_t cbbase = (size_t)(((b * 8 + c) * 8) + g) * (CHUNK * CHUNK);

    {
        float av = g_A[(tokbase + tid) * NHEAD + h];
        float atot;
        float acs = scan256(av, wps, &atot);
        sAcs[tid] = acs;
    }
    __syncthreads();

    int ty = tid >> 5, tx = tid & 31;     // compute mapping: rows 4ty..4ty+3, d 2tx..2tx+1
    int bi = tid >> 4, bj = tid & 15;     // fill mapping

    for (int t0 = 0; t0 < 8; t0++) {
        __syncthreads();
        // C tile transposed load: sCtT[n][i]
        #pragma unroll
        for (int k = 0; k < 4; k++) {
            int q = tid + k * 256;
            int chunk = q >> 5, i = q & 31;
            float4 v = *(const float4*)&g_conv[(tokbase + t0 * 32 + i) * CONVDIM + CCOL_C + g * 128 + chunk * 4];
            sCtT[chunk * 4 + 0][i] = v.x;
            sCtT[chunk * 4 + 1][i] = v.y;
            sCtT[chunk * 4 + 2][i] = v.z;
            sCtT[chunk * 4 + 3][i] = v.w;
        }
        // factor tables (anchor = start of t tile)
        float ar = sAcs[t0 * 32];
        if (tid < 32) fr[tid] = expf(sAcs[t0 * 32 + tid] - ar);
        if (tid < t0 * 32) gc[tid] = expf(ar - sAcs[tid]);
        __syncthreads();

        float accD[4][2] = {{0.f,0.f},{0.f,0.f},{0.f,0.f},{0.f,0.f}};
        float acc2[4][2] = {{0.f,0.f},{0.f,0.f},{0.f,0.f},{0.f,0.f}};

        for (int s0 = 0; s0 <= t0; s0++) {
            // load X tile for s0
            #pragma unroll
            for (int k = 0; k < 2; k++) {
                int q = tid + k * 256; int j = q >> 4, d4 = (q & 15) << 2;
                *(float4*)&sX[j][d4] =
                    *(const float4*)&g_conv[(tokbase + s0 * 32 + j) * CONVDIM + h * 64 + d4];
            }
            // fill sM[s][t] from g_CB with decay scaling
            {
                int i0 = 2 * bi, j0 = 2 * bj;
                size_t r0 = cbbase + (size_t)(t0 * 32 + i0) * CHUNK + s0 * 32 + j0;
                float2 m0 = *(const float2*)&g_CB[r0];
                float2 m1 = *(const float2*)&g_CB[r0 + CHUNK];
                if (s0 < t0) {
                    float f0 = fr[i0], f1 = fr[i0 + 1];
                    float g0 = gc[s0 * 32 + j0], g1 = gc[s0 * 32 + j0 + 1];
                    sM[j0][i0]         = m0.x * f0 * g0;
                    sM[j0 + 1][i0]     = m0.y * f0 * g1;
                    sM[j0][i0 + 1]     = m1.x * f1 * g0;
                    sM[j0 + 1][i0 + 1] = m1.y * f1 * g1;
                } else {
                    float at0 = sAcs[t0 * 32 + i0], at1 = sAcs[t0 * 32 + i0 + 1];
                    float as0 = sAcs[s0 * 32 + j0], as1 = sAcs[s0 * 32 + j0 + 1];
                    sM[j0][i0]         = (j0     <= i0    ) ? m0.x * expf(at0 - as0) : 0.f;
                    sM[j0 + 1][i0]     = (j0 + 1 <= i0    ) ? m0.y * expf(at0 - as1) : 0.f;
                    sM[j0][i0 + 1]     = (j0     <= i0 + 1) ? m1.x * expf(at1 - as0) : 0.f;
                    sM[j0 + 1][i0 + 1] = (j0 + 1 <= i0 + 1) ? m1.y * expf(at1 - as1) : 0.f;
                }
            }
            __syncthreads();
            // accD += M^T @ X : vectorized (broadcast float4 M + float2 X)
            #pragma unroll
            for (int k = 0; k < 32; k++) {
                float4 mv = *(const float4*)&sM[k][4 * ty];
                float2 xv = *(const float2*)&sX[k][2 * tx];
                accD[0][0] += mv.x * xv.x; accD[0][1] += mv.x * xv.y;
                accD[1][0] += mv.y * xv.x; accD[1][1] += mv.y * xv.y;
                accD[2][0] += mv.z * xv.x; accD[2][1] += mv.z * xv.y;
                accD[3][0] += mv.w * xv.x; accD[3][1] += mv.w * xv.y;
            }
            __syncthreads();
        }
        // carry: acc2 += C_t @ h_prev, staged in 4 quarters of 32 n
        for (int qh = 0; qh < 4; qh++) {
            #pragma unroll
            for (int k = 0; k < 2; k++) {
                int q = tid + k * 256; int nl = q >> 4, d4 = (q & 15) << 2;
                *(float4*)&sH[nl * 64 + d4] =
                    *(const float4*)&g_hprev[(chb * NSTATE + qh * 32 + nl) * DHEAD + d4];
            }
            __syncthreads();
            #pragma unroll
            for (int k = 0; k < 32; k++) {
                int n = qh * 32 + k;
                float4 cv = *(const float4*)&sCtT[n][4 * ty];
                float2 hv = *(const float2*)&sH[k * 64 + 2 * tx];
                acc2[0][0] += cv.x * hv.x; acc2[0][1] += cv.x * hv.y;
                acc2[1][0] += cv.y * hv.x; acc2[1][1] += cv.y * hv.y;
                acc2[2][0] += cv.z * hv.x; acc2[2][1] += cv.z * hv.y;
                acc2[3][0] += cv.w * hv.x; acc2[3][1] += cv.w * hv.y;
            }
            __syncthreads();
        }
        // write Y
        #pragma unroll
        for (int r = 0; r < 4; r++) {
            int t = t0 * 32 + 4 * ty + r;
            float e = expf(sAcs[t]);
            size_t off = (tokbase + t) * DINNER + h * 64 + 2 * tx;
            g_Y[off]     = accD[r][0] + acc2[r][0] * e;
            g_Y[off + 1] = accD[r][1] + acc2[r][1] * e;
        }
    }
}

// ---------------- K8: out rmsnorm * silu(gate) -> bf16 split into g_a2 --------
__global__ __launch_bounds__(256) void k_gate(const float* __restrict__ onw) {
    int t = blockIdx.x;
    float vloc[16];
    float ss = 0.f;
    #pragma unroll
    for (int j = 0; j < 16; j++) {
        float v = g_Y[(size_t)t * DINNER + threadIdx.x + j * 256];
        vloc[j] = v;
        ss += v * v;
    }
    float tot = block_reduce_sum_256(ss);
    float r = rsqrtf(tot * (1.f / DINNER) + 1e-6f);
    size_t base = (size_t)t * (3 * DINNER);
    #pragma unroll
    for (int j = 0; j < 16; j++) {
        int k = threadIdx.x + j * 256;
        float y = vloc[j] * r * onw[k];
        float gt = g_proj[(size_t)t * INPROJ + COL_GATE + k];
        float v = y * gt / (1.f + expf(-gt));
        __nv_bfloat16 hi = __float2bfloat16(v);
        __nv_bfloat16 lo = __float2bfloat16(v - __bfloat162float(hi));
        g_a2[base + k] = hi;
        g_a2[base + DINNER + k] = hi;
        g_a2[base + 2 * DINNER + k] = lo;
    }
}

// ---------------- launch ----------------
extern "C" void kernel_launch(void* const* d_in, const int* in_sizes, int n_in,
                              void* d_out, int out_size) {
    const float* x          = (const float*)d_in[0];
    const float* norm_w     = (const float*)d_in[1];
    const float* in_proj_w  = (const float*)d_in[2];
    const float* conv_w     = (const float*)d_in[3];
    const float* conv_b     = (const float*)d_in[4];
    const float* conv_norm_w= (const float*)d_in[5];
    const float* A_log      = (const float*)d_in[6];
    const float* dt_w       = (const float*)d_in[7];
    const float* dt_b       = (const float*)d_in[8];
    const float* out_norm_w = (const float*)d_in[9];
    const float* out_proj_w = (const float*)d_in[10];
    float* out = (float*)d_out;

    float* hfin = (out_size >= OUT_ELEMS + HFIN_ELEMS) ? (out + OUT_ELEMS) : nullptr;

    k_rms_in<<<TTOK, 256>>>(x, norm_w);
    k_cvt<<<(unsigned)(((size_t)INPROJ_PAD * DMODEL) / 256), 256>>>(1, in_proj_w, INPROJ, DMODEL);
    k_hgemm<<<dim3(INPROJ_PAD / 128, TTOK / 128), 256>>>(0, 0, nullptr, nullptr, TTOK, INPROJ, 3 * DMODEL);

    k_conv<<<TTOK, 256>>>(conv_w, conv_b, conv_norm_w);
    k_dt<<<TTOK / 4, 256>>>(dt_w, dt_b, A_log);
    k_cb<<<Bb * NCHUNK * NGRP, 256>>>();
    k_states<<<Bb * NCHUNK * NHEAD, 256>>>();
    k_scan<<<Bb * NHEAD, 256>>>(hfin);
    k_ydiag<<<Bb * NCHUNK * NHEAD, 256>>>();
    k_gate<<<TTOK, 256>>>(out_norm_w);

    k_cvt<<<(unsigned)(((size_t)DMODEL * DINNER) / 256), 256>>>(2, out_proj_w, DMODEL, DINNER);
    k_hgemm<<<dim3(DMODEL / 128, TTOK / 128), 256>>>(1, 1, out, x, TTOK, DMODEL, 3 * DINNER);
}